// round 5
// baseline (speedup 1.0000x reference)
#include <cuda_runtime.h>
#include <math.h>

// Problem constants: B=1, N=256, C_in=128, H=4, D=32
#define NRES 256
#define CIN  128
#define NH   4
#define DH   32
#define HD   128              // NH*DH
#define M_TOT (NRES * NRES)   // 65536 rows

// ---------------- scratch (static device globals; no allocation) ------------
__device__ float g_q[NRES * NH * NRES * DH];    // [n][h][q][d], pre-scaled
__device__ float g_k[NRES * NH * NRES * DH];    // [n][h][k][d]
__device__ float g_v[NRES * NH * NRES * DH];    // [n][h][k][d]
__device__ float g_gate[M_TOT * HD];            // [n*256+q][h*32+d], sigmoid applied
__device__ float g_o[M_TOT * HD];               // [n*256+q][h*32+d], attention out

// ---------------- tiled SGEMM config ----------------------------------------
#define BM 128
#define BN 128
#define BK 32
// 256 threads = 16x16, each computes 8x8 outputs

// Projections: modes 0=q (scaled), 1=k, 2=v, 3=gate (sigmoid(x+bg))
__global__ __launch_bounds__(256)
void proj_kernel(const float* __restrict__ q_x, const float* __restrict__ kv_x,
                 const float* __restrict__ wq, const float* __restrict__ wk,
                 const float* __restrict__ wv, const float* __restrict__ wg,
                 const float* __restrict__ bg)
{
    __shared__ float As[BK][BM + 4];   // [k][m], stride 132 (float4-aligned)
    __shared__ float Bs[BK][BN + 4];   // [k][n]

    const int mode = blockIdx.y;
    const float* A = (mode == 1 || mode == 2) ? kv_x : q_x;
    const float* W = (mode == 0) ? wq : (mode == 1) ? wk : (mode == 2) ? wv : wg;

    const int tid = threadIdx.x;
    const int tx = tid & 15;          // output col group
    const int ty = tid >> 4;          // output row group
    const int m0 = blockIdx.x * BM;
    const int ka = tid & 31;          // k within chunk (coalesced global)
    const int ia = tid >> 5;          // 0..7

    float acc[8][8];
#pragma unroll
    for (int i = 0; i < 8; i++)
#pragma unroll
        for (int j = 0; j < 8; j++) acc[i][j] = 0.f;

    for (int k0 = 0; k0 < CIN; k0 += BK) {
#pragma unroll
        for (int i = 0; i < 16; i++) {
            int m = ia + i * 8;
            As[ka][m] = A[(size_t)(m0 + m) * CIN + k0 + ka];
            Bs[ka][m] = W[m * CIN + k0 + ka];
        }
        __syncthreads();
#pragma unroll
        for (int kk = 0; kk < BK; kk++) {
            float a[8], b[8];
            *(float4*)&a[0] = *(float4*)&As[kk][ty * 8];
            *(float4*)&a[4] = *(float4*)&As[kk][ty * 8 + 4];
            *(float4*)&b[0] = *(float4*)&Bs[kk][tx * 8];
            *(float4*)&b[4] = *(float4*)&Bs[kk][tx * 8 + 4];
#pragma unroll
            for (int i = 0; i < 8; i++)
#pragma unroll
                for (int j = 0; j < 8; j++) acc[i][j] += a[i] * b[j];
        }
        __syncthreads();
    }

    const int col0 = tx * 8;
    if (mode < 3) {
        const float scale = (mode == 0) ? 0.17677669529663687f : 1.0f;  // 1/sqrt(32)
        float* dst = (mode == 0) ? g_q : (mode == 1) ? g_k : g_v;
        const int h  = col0 >> 5;
        const int d0 = col0 & 31;     // 8 cols stay within one head
#pragma unroll
        for (int i = 0; i < 8; i++) {
            int mrow = m0 + ty * 8 + i;
            int n = mrow >> 8, r = mrow & 255;
            float* p = dst + (((size_t)(n * NH + h) * NRES + r) * DH + d0);
            float4 v0 = make_float4(acc[i][0] * scale, acc[i][1] * scale,
                                    acc[i][2] * scale, acc[i][3] * scale);
            float4 v1 = make_float4(acc[i][4] * scale, acc[i][5] * scale,
                                    acc[i][6] * scale, acc[i][7] * scale);
            *(float4*)p = v0;
            *(float4*)(p + 4) = v1;
        }
    } else {
        float bgv[8];
#pragma unroll
        for (int j = 0; j < 8; j++) bgv[j] = bg[col0 + j];
#pragma unroll
        for (int i = 0; i < 8; i++) {
            int mrow = m0 + ty * 8 + i;
            float* p = g_gate + (size_t)mrow * HD + col0;
            float v[8];
#pragma unroll
            for (int j = 0; j < 8; j++) {
                float x = acc[i][j] + bgv[j];
                v[j] = 1.0f / (1.0f + __expf(-x));
            }
            *(float4*)p       = make_float4(v[0], v[1], v[2], v[3]);
            *(float4*)(p + 4) = make_float4(v[4], v[5], v[6], v[7]);
        }
    }
}

// Output projection with gating fused into the A-tile load:
// out[m][c] = sum_e (g_o[m][e]*g_gate[m][e]) * wo[c][e] + bo[c]
__global__ __launch_bounds__(256)
void outproj_kernel(const float* __restrict__ wo, const float* __restrict__ bo,
                    float* __restrict__ out)
{
    __shared__ float As[BK][BM + 4];
    __shared__ float Bs[BK][BN + 4];

    const int tid = threadIdx.x;
    const int tx = tid & 15, ty = tid >> 4;
    const int m0 = blockIdx.x * BM;
    const int ka = tid & 31, ia = tid >> 5;

    float acc[8][8];
#pragma unroll
    for (int i = 0; i < 8; i++)
#pragma unroll
        for (int j = 0; j < 8; j++) acc[i][j] = 0.f;

    for (int k0 = 0; k0 < HD; k0 += BK) {
#pragma unroll
        for (int i = 0; i < 16; i++) {
            int m = ia + i * 8;
            size_t idx = (size_t)(m0 + m) * HD + k0 + ka;
            As[ka][m] = g_o[idx] * g_gate[idx];
            Bs[ka][m] = wo[m * HD + k0 + ka];
        }
        __syncthreads();
#pragma unroll
        for (int kk = 0; kk < BK; kk++) {
            float a[8], b[8];
            *(float4*)&a[0] = *(float4*)&As[kk][ty * 8];
            *(float4*)&a[4] = *(float4*)&As[kk][ty * 8 + 4];
            *(float4*)&b[0] = *(float4*)&Bs[kk][tx * 8];
            *(float4*)&b[4] = *(float4*)&Bs[kk][tx * 8 + 4];
#pragma unroll
            for (int i = 0; i < 8; i++)
#pragma unroll
                for (int j = 0; j < 8; j++) acc[i][j] += a[i] * b[j];
        }
        __syncthreads();
    }

    const int col0 = tx * 8;
    float bov[8];
#pragma unroll
    for (int j = 0; j < 8; j++) bov[j] = bo[col0 + j];
#pragma unroll
    for (int i = 0; i < 8; i++) {
        int mrow = m0 + ty * 8 + i;
        float* p = out + (size_t)mrow * HD + col0;
        *(float4*)p       = make_float4(acc[i][0] + bov[0], acc[i][1] + bov[1],
                                        acc[i][2] + bov[2], acc[i][3] + bov[3]);
        *(float4*)(p + 4) = make_float4(acc[i][4] + bov[4], acc[i][5] + bov[5],
                                        acc[i][6] + bov[6], acc[i][7] + bov[7]);
    }
}

// Fused attention: one block per (n,h), one thread per q row, online softmax.
// K/V and (triangle+mask) bias staged through smem in 32-wide k chunks with
// register-prefetch software pipelining (next chunk's LDGs overlap compute).
// Softmax rescale amortized over 8-k sub-chunks; rescale skipped (bit-exact)
// when the sub-chunk max does not raise the running max.
__global__ __launch_bounds__(256, 2)
void attn_kernel(const float* __restrict__ mask_bias,
                 const float* __restrict__ tri)
{
    const int n = blockIdx.x;
    const int h = blockIdx.y;
    const int q = threadIdx.x;   // 0..255

    __shared__ float Ks[32][36];      // [kk][d], padded
    __shared__ float Vs[32][36];
    __shared__ float Ts[NRES * 33];   // (tri+mask) chunk: [q][kk], stride 33
    __shared__ float MB[NRES];        // mask bias row for this n

    const size_t base = (size_t)(n * NH + h) * NRES * DH;
    const float* Qg = g_q + base;
    const float* Kg = g_k + base;
    const float* Vg = g_v + base;

    float qv[32];
#pragma unroll
    for (int i = 0; i < 8; i++)
        ((float4*)qv)[i] = ((const float4*)(Qg + q * DH))[i];
    MB[q] = mask_bias[n * NRES + q];

    float mx = -1e30f, l = 0.f;
    float o[32];
#pragma unroll
    for (int d = 0; d < 32; d++) o[d] = 0.f;

    const int lr  = threadIdx.x >> 3;        // 0..31
    const int lc4 = (threadIdx.x & 7) * 4;   // 0,4,...,28
    const float* trib = tri + (size_t)(h * NRES) * NRES;

    // ---- prefetch chunk 0 into registers ----
    float4 kpre = *(const float4*)(Kg + lr * DH + lc4);
    float4 vpre = *(const float4*)(Vg + lr * DH + lc4);
    float4 tpre[8];
#pragma unroll
    for (int i = 0; i < 8; i++)
        tpre[i] = *(const float4*)(trib + (size_t)(lr + i * 32) * NRES + lc4);

    for (int k0 = 0; k0 < NRES; k0 += 32) {
        __syncthreads();   // previous chunk consumers done (also orders MB write)
        // ---- store prefetched chunk; fold mask bias into Ts ----
        *(float4*)&Ks[lr][lc4] = kpre;
        *(float4*)&Vs[lr][lc4] = vpre;
        float m0b = MB[k0 + lc4], m1b = MB[k0 + lc4 + 1];
        float m2b = MB[k0 + lc4 + 2], m3b = MB[k0 + lc4 + 3];
#pragma unroll
        for (int i = 0; i < 8; i++) {
            float* tp = &Ts[(lr + i * 32) * 33 + lc4];
            tp[0] = tpre[i].x + m0b; tp[1] = tpre[i].y + m1b;
            tp[2] = tpre[i].z + m2b; tp[3] = tpre[i].w + m3b;
        }
        __syncthreads();
        // ---- issue next chunk's loads (overlap with compute below) ----
        int kn = k0 + 32;
        if (kn < NRES) {
            kpre = *(const float4*)(Kg + (kn + lr) * DH + lc4);
            vpre = *(const float4*)(Vg + (kn + lr) * DH + lc4);
#pragma unroll
            for (int i = 0; i < 8; i++)
                tpre[i] = *(const float4*)(trib + (size_t)(lr + i * 32) * NRES + kn + lc4);
        }

#pragma unroll
        for (int kc = 0; kc < 32; kc += 8) {
            // --- phase 1: 8 scores into registers ---
            float s[8];
#pragma unroll
            for (int j = 0; j < 8; j++) {
                int kk = kc + j;
                float acc = Ts[q * 33 + kk];
#pragma unroll
                for (int d = 0; d < 32; d += 4) {
                    float4 k4 = *(float4*)&Ks[kk][d];   // broadcast across lanes
                    acc += qv[d] * k4.x + qv[d + 1] * k4.y
                         + qv[d + 2] * k4.z + qv[d + 3] * k4.w;
                }
                s[j] = acc;
            }
            // --- phase 2: sub-chunk max; rescale only if running max rises ---
            float cmax = s[0];
#pragma unroll
            for (int j = 1; j < 8; j++) cmax = fmaxf(cmax, s[j]);
            if (cmax > mx) {
                float corr = __expf(mx - cmax);   // exact no-op path skipped
                mx = cmax;
                l *= corr;
#pragma unroll
                for (int d = 0; d < 32; d++) o[d] *= corr;
            }
            // --- phase 3: pure-FMA accumulate ---
#pragma unroll
            for (int j = 0; j < 8; j++) {
                int kk = kc + j;
                float p = __expf(s[j] - mx);
                l += p;
#pragma unroll
                for (int d = 0; d < 32; d += 4) {
                    float4 v4 = *(float4*)&Vs[kk][d];
                    o[d]     += p * v4.x;
                    o[d + 1] += p * v4.y;
                    o[d + 2] += p * v4.z;
                    o[d + 3] += p * v4.w;
                }
            }
        }
    }

    const float inv = 1.0f / l;
    float* Og = g_o + ((size_t)(n * NRES + q)) * HD + h * DH;
#pragma unroll
    for (int d = 0; d < 32; d += 4) {
        *(float4*)(Og + d) = make_float4(o[d] * inv, o[d + 1] * inv,
                                         o[d + 2] * inv, o[d + 3] * inv);
    }
}

// ---------------------------------------------------------------------------
extern "C" void kernel_launch(void* const* d_in, const int* in_sizes, int n_in,
                              void* d_out, int out_size)
{
    (void)in_sizes; (void)n_in; (void)out_size;
    const float* q_x  = (const float*)d_in[0];
    const float* kv_x = (const float*)d_in[1];
    const float* mask = (const float*)d_in[2];
    const float* tri  = (const float*)d_in[3];
    const float* wq   = (const float*)d_in[4];
    const float* wk   = (const float*)d_in[5];
    const float* wv   = (const float*)d_in[6];
    const float* wg   = (const float*)d_in[7];
    const float* bg   = (const float*)d_in[8];
    const float* wo   = (const float*)d_in[9];
    const float* bo   = (const float*)d_in[10];
    float* out = (float*)d_out;

    proj_kernel<<<dim3(M_TOT / BM, 4), 256>>>(q_x, kv_x, wq, wk, wv, wg, bg);
    attn_kernel<<<dim3(NRES, NH), 256>>>(mask, tri);
    outproj_kernel<<<dim3(M_TOT / BM), 256>>>(wo, bo, out);
}

// round 7
// speedup vs baseline: 1.2228x; 1.2228x over previous
#include <cuda_runtime.h>
#include <math.h>

// Problem constants: B=1, N=256, C_in=128, H=4, D=32
#define NRES 256
#define CIN  128
#define NH   4
#define DH   32
#define HD   128              // NH*DH
#define M_TOT (NRES * NRES)   // 65536 rows

typedef unsigned long long u64t;

// ---------------- packed f32x2 helpers (sm_100+ PTX; 2 FMAs per issue) ------
__device__ __forceinline__ u64t pack2(float lo, float hi) {
    u64t r; asm("mov.b64 %0, {%1, %2};" : "=l"(r) : "f"(lo), "f"(hi)); return r;
}
__device__ __forceinline__ u64t pack2r(float v) { return pack2(v, v); }
__device__ __forceinline__ void unpack2(u64t p, float& lo, float& hi) {
    asm("mov.b64 {%0, %1}, %2;" : "=f"(lo), "=f"(hi) : "l"(p));
}
__device__ __forceinline__ u64t ffma2_(u64t a, u64t b, u64t c) {
    u64t d; asm("fma.rn.f32x2 %0, %1, %2, %3;" : "=l"(d) : "l"(a), "l"(b), "l"(c)); return d;
}
__device__ __forceinline__ u64t fmul2_(u64t a, u64t b) {
    u64t d; asm("mul.rn.f32x2 %0, %1, %2;" : "=l"(d) : "l"(a), "l"(b)); return d;
}
__device__ __forceinline__ u64t fadd2_(u64t a, u64t b) {
    u64t d; asm("add.rn.f32x2 %0, %1, %2;" : "=l"(d) : "l"(a), "l"(b)); return d;
}

// ---------------- scratch (static device globals; no allocation) ------------
__device__ float g_q[NRES * NH * NRES * DH];    // [n][h][q][d], pre-scaled
__device__ float g_k[NRES * NH * NRES * DH];    // [n][h][k][d]
__device__ float g_v[NRES * NH * NRES * DH];    // [n][h][k][d]
__device__ float g_gate[M_TOT * HD];            // [n*256+q][h*32+d], sigmoid applied
__device__ float g_o[M_TOT * HD];               // [n*256+q][h*32+d], attention out

// ---------------- tiled SGEMM config ----------------------------------------
#define BM 128
#define BN 128
#define BK 32
// 256 threads = 16x16, each computes 8x8 outputs (acc packed as 8x4 f32x2)

// Projections: modes 0=q (scaled), 1=k, 2=v, 3=gate (sigmoid(x+bg))
__global__ __launch_bounds__(256, 2)
void proj_kernel(const float* __restrict__ q_x, const float* __restrict__ kv_x,
                 const float* __restrict__ wq, const float* __restrict__ wk,
                 const float* __restrict__ wv, const float* __restrict__ wg,
                 const float* __restrict__ bg)
{
    __shared__ float As[BK][BM + 4];   // [k][m], stride 132 floats (16B-aligned rows)
    __shared__ float Bs[BK][BN + 4];

    const int mode = blockIdx.y;
    const float* A = (mode == 1 || mode == 2) ? kv_x : q_x;
    const float* W = (mode == 0) ? wq : (mode == 1) ? wk : (mode == 2) ? wv : wg;

    const int tid = threadIdx.x;
    const int tx = tid & 15;          // output col group
    const int ty = tid >> 4;          // output row group
    const int m0 = blockIdx.x * BM;
    const int ka = tid & 31;          // k within chunk (coalesced global)
    const int ia = tid >> 5;          // 0..7

    u64t acc2[8][4];                  // [row][colpair], each = 2 fp32
#pragma unroll
    for (int i = 0; i < 8; i++)
#pragma unroll
        for (int jp = 0; jp < 4; jp++) acc2[i][jp] = 0ull;

    for (int k0 = 0; k0 < CIN; k0 += BK) {
#pragma unroll
        for (int i = 0; i < 16; i++) {
            int m = ia + i * 8;
            As[ka][m] = A[(size_t)(m0 + m) * CIN + k0 + ka];
            Bs[ka][m] = W[m * CIN + k0 + ka];
        }
        __syncthreads();
#pragma unroll
        for (int kk = 0; kk < BK; kk++) {
            float a[8];
            *(float4*)&a[0] = *(float4*)&As[kk][ty * 8];
            *(float4*)&a[4] = *(float4*)&As[kk][ty * 8 + 4];
            ulonglong2 b01 = *(ulonglong2*)&Bs[kk][tx * 8];
            ulonglong2 b23 = *(ulonglong2*)&Bs[kk][tx * 8 + 4];
            u64t b2[4] = {b01.x, b01.y, b23.x, b23.y};
#pragma unroll
            for (int i = 0; i < 8; i++) {
                u64t a2 = pack2r(a[i]);
#pragma unroll
                for (int jp = 0; jp < 4; jp++)
                    acc2[i][jp] = ffma2_(a2, b2[jp], acc2[i][jp]);
            }
        }
        __syncthreads();
    }

    const int col0 = tx * 8;
    if (mode < 3) {
        const float scale = (mode == 0) ? 0.17677669529663687f : 1.0f;  // 1/sqrt(32)
        float* dst = (mode == 0) ? g_q : (mode == 1) ? g_k : g_v;
        const int h  = col0 >> 5;
        const int d0 = col0 & 31;     // 8 cols stay within one head
        const u64t scale2 = pack2r(scale);
#pragma unroll
        for (int i = 0; i < 8; i++) {
            int mrow = m0 + ty * 8 + i;
            int n = mrow >> 8, r = mrow & 255;
            float* p = dst + (((size_t)(n * NH + h) * NRES + r) * DH + d0);
            ulonglong2 s0, s1;
            s0.x = fmul2_(acc2[i][0], scale2);
            s0.y = fmul2_(acc2[i][1], scale2);
            s1.x = fmul2_(acc2[i][2], scale2);
            s1.y = fmul2_(acc2[i][3], scale2);
            *(ulonglong2*)p       = s0;
            *(ulonglong2*)(p + 4) = s1;
        }
    } else {
        float bgv[8];
#pragma unroll
        for (int j = 0; j < 8; j++) bgv[j] = bg[col0 + j];
#pragma unroll
        for (int i = 0; i < 8; i++) {
            int mrow = m0 + ty * 8 + i;
            float* p = g_gate + (size_t)mrow * HD + col0;
            float v[8];
            unpack2(acc2[i][0], v[0], v[1]);
            unpack2(acc2[i][1], v[2], v[3]);
            unpack2(acc2[i][2], v[4], v[5]);
            unpack2(acc2[i][3], v[6], v[7]);
#pragma unroll
            for (int j = 0; j < 8; j++) {
                float x = v[j] + bgv[j];
                v[j] = 1.0f / (1.0f + __expf(-x));
            }
            *(float4*)p       = make_float4(v[0], v[1], v[2], v[3]);
            *(float4*)(p + 4) = make_float4(v[4], v[5], v[6], v[7]);
        }
    }
}

// Output projection with gating fused into the A-tile load:
// out[m][c] = sum_e (g_o[m][e]*g_gate[m][e]) * wo[c][e] + bo[c]
__global__ __launch_bounds__(256, 2)
void outproj_kernel(const float* __restrict__ wo, const float* __restrict__ bo,
                    float* __restrict__ out)
{
    __shared__ float As[BK][BM + 4];
    __shared__ float Bs[BK][BN + 4];

    const int tid = threadIdx.x;
    const int tx = tid & 15, ty = tid >> 4;
    const int m0 = blockIdx.x * BM;
    const int ka = tid & 31, ia = tid >> 5;

    u64t acc2[8][4];
#pragma unroll
    for (int i = 0; i < 8; i++)
#pragma unroll
        for (int jp = 0; jp < 4; jp++) acc2[i][jp] = 0ull;

    for (int k0 = 0; k0 < HD; k0 += BK) {
#pragma unroll
        for (int i = 0; i < 16; i++) {
            int m = ia + i * 8;
            size_t idx = (size_t)(m0 + m) * HD + k0 + ka;
            As[ka][m] = g_o[idx] * g_gate[idx];
            Bs[ka][m] = wo[m * HD + k0 + ka];
        }
        __syncthreads();
#pragma unroll
        for (int kk = 0; kk < BK; kk++) {
            float a[8];
            *(float4*)&a[0] = *(float4*)&As[kk][ty * 8];
            *(float4*)&a[4] = *(float4*)&As[kk][ty * 8 + 4];
            ulonglong2 b01 = *(ulonglong2*)&Bs[kk][tx * 8];
            ulonglong2 b23 = *(ulonglong2*)&Bs[kk][tx * 8 + 4];
            u64t b2[4] = {b01.x, b01.y, b23.x, b23.y};
#pragma unroll
            for (int i = 0; i < 8; i++) {
                u64t a2 = pack2r(a[i]);
#pragma unroll
                for (int jp = 0; jp < 4; jp++)
                    acc2[i][jp] = ffma2_(a2, b2[jp], acc2[i][jp]);
            }
        }
        __syncthreads();
    }

    const int col0 = tx * 8;
    ulonglong2 bo01 = *(const ulonglong2*)(bo + col0);
    ulonglong2 bo23 = *(const ulonglong2*)(bo + col0 + 4);
    u64t bo2[4] = {bo01.x, bo01.y, bo23.x, bo23.y};
#pragma unroll
    for (int i = 0; i < 8; i++) {
        int mrow = m0 + ty * 8 + i;
        float* p = out + (size_t)mrow * HD + col0;
        ulonglong2 s0, s1;
        s0.x = fadd2_(acc2[i][0], bo2[0]);
        s0.y = fadd2_(acc2[i][1], bo2[1]);
        s1.x = fadd2_(acc2[i][2], bo2[2]);
        s1.y = fadd2_(acc2[i][3], bo2[3]);
        *(ulonglong2*)p       = s0;
        *(ulonglong2*)(p + 4) = s1;
    }
}

// Fused attention: one block per (n,h), one thread per q row, online softmax.
// K/V and (triangle+mask) bias staged through smem in 32-wide k chunks with
// register-prefetch software pipelining. All score/accumulate math in packed
// f32x2 (half the FMA issue count). Rescale amortized per 8-k sub-chunk and
// skipped (bit-exact) when the running max does not rise.
__global__ __launch_bounds__(256, 2)
void attn_kernel(const float* __restrict__ mask_bias,
                 const float* __restrict__ tri)
{
    const int n = blockIdx.x;
    const int h = blockIdx.y;
    const int q = threadIdx.x;   // 0..255

    __shared__ float Ks[32][36];      // [kk][d], padded, rows 16B-aligned
    __shared__ float Vs[32][36];
    __shared__ float Ts[NRES * 33];   // (tri+mask) chunk: [q][kk], stride 33
    __shared__ float MB[NRES];        // mask bias row for this n

    const size_t base = (size_t)(n * NH + h) * NRES * DH;
    const float* Qg = g_q + base;
    const float* Kg = g_k + base;
    const float* Vg = g_v + base;

    u64t qv2[16];                     // q row packed along d
#pragma unroll
    for (int i = 0; i < 8; i++) {
        ulonglong2 t = ((const ulonglong2*)(Qg + q * DH))[i];
        qv2[i * 2] = t.x; qv2[i * 2 + 1] = t.y;
    }
    MB[q] = mask_bias[n * NRES + q];

    float mx = -1e30f, l = 0.f;
    u64t o2[16];
#pragma unroll
    for (int dp = 0; dp < 16; dp++) o2[dp] = 0ull;

    const int lr  = threadIdx.x >> 3;        // 0..31
    const int lc4 = (threadIdx.x & 7) * 4;   // 0,4,...,28
    const float* trib = tri + (size_t)(h * NRES) * NRES;

    // ---- prefetch chunk 0 into registers ----
    float4 kpre = *(const float4*)(Kg + lr * DH + lc4);
    float4 vpre = *(const float4*)(Vg + lr * DH + lc4);
    float4 tpre[8];
#pragma unroll
    for (int i = 0; i < 8; i++)
        tpre[i] = *(const float4*)(trib + (size_t)(lr + i * 32) * NRES + lc4);

    for (int k0 = 0; k0 < NRES; k0 += 32) {
        __syncthreads();   // previous chunk consumers done (also orders MB write)
        *(float4*)&Ks[lr][lc4] = kpre;
        *(float4*)&Vs[lr][lc4] = vpre;
        float m0b = MB[k0 + lc4], m1b = MB[k0 + lc4 + 1];
        float m2b = MB[k0 + lc4 + 2], m3b = MB[k0 + lc4 + 3];
#pragma unroll
        for (int i = 0; i < 8; i++) {
            float* tp = &Ts[(lr + i * 32) * 33 + lc4];
            tp[0] = tpre[i].x + m0b; tp[1] = tpre[i].y + m1b;
            tp[2] = tpre[i].z + m2b; tp[3] = tpre[i].w + m3b;
        }
        __syncthreads();
        // ---- issue next chunk's loads (overlap with compute below) ----
        int kn = k0 + 32;
        if (kn < NRES) {
            kpre = *(const float4*)(Kg + (kn + lr) * DH + lc4);
            vpre = *(const float4*)(Vg + (kn + lr) * DH + lc4);
#pragma unroll
            for (int i = 0; i < 8; i++)
                tpre[i] = *(const float4*)(trib + (size_t)(lr + i * 32) * NRES + kn + lc4);
        }

#pragma unroll
        for (int kc = 0; kc < 32; kc += 8) {
            // --- phase 1: 8 scores, packed dual accumulators ---
            float s[8];
#pragma unroll
            for (int j = 0; j < 8; j++) {
                int kk = kc + j;
                u64t accA = 0ull, accB = 0ull;
#pragma unroll
                for (int d = 0; d < 32; d += 4) {
                    ulonglong2 k2 = *(ulonglong2*)&Ks[kk][d];   // broadcast
                    accA = ffma2_(qv2[d >> 1], k2.x, accA);
                    accB = ffma2_(qv2[(d >> 1) + 1], k2.y, accB);
                }
                float aLo, aHi, bLo, bHi;
                unpack2(accA, aLo, aHi);
                unpack2(accB, bLo, bHi);
                s[j] = Ts[q * 33 + kk] + ((aLo + aHi) + (bLo + bHi));
            }
            // --- phase 2: sub-chunk max; rescale only if running max rises ---
            float cmax = s[0];
#pragma unroll
            for (int j = 1; j < 8; j++) cmax = fmaxf(cmax, s[j]);
            if (cmax > mx) {
                float corr = __expf(mx - cmax);   // exact no-op path skipped
                mx = cmax;
                l *= corr;
                u64t corr2 = pack2r(corr);
#pragma unroll
                for (int dp = 0; dp < 16; dp++) o2[dp] = fmul2_(o2[dp], corr2);
            }
            // --- phase 3: packed-FMA accumulate ---
#pragma unroll
            for (int j = 0; j < 8; j++) {
                int kk = kc + j;
                float p = __expf(s[j] - mx);
                l += p;
                u64t p2 = pack2r(p);
#pragma unroll
                for (int d = 0; d < 32; d += 4) {
                    ulonglong2 v2 = *(ulonglong2*)&Vs[kk][d];
                    o2[d >> 1]       = ffma2_(p2, v2.x, o2[d >> 1]);
                    o2[(d >> 1) + 1] = ffma2_(p2, v2.y, o2[(d >> 1) + 1]);
                }
            }
        }
    }

    const float inv = 1.0f / l;
    const u64t inv2 = pack2r(inv);
    float* Og = g_o + ((size_t)(n * NRES + q)) * HD + h * DH;
#pragma unroll
    for (int dp = 0; dp < 16; dp += 2) {
        ulonglong2 st;
        st.x = fmul2_(o2[dp], inv2);
        st.y = fmul2_(o2[dp + 1], inv2);
        *(ulonglong2*)(Og + dp * 2) = st;
    }
}

// ---------------------------------------------------------------------------
extern "C" void kernel_launch(void* const* d_in, const int* in_sizes, int n_in,
                              void* d_out, int out_size)
{
    (void)in_sizes; (void)n_in; (void)out_size;
    const float* q_x  = (const float*)d_in[0];
    const float* kv_x = (const float*)d_in[1];
    const float* mask = (const float*)d_in[2];
    const float* tri  = (const float*)d_in[3];
    const float* wq   = (const float*)d_in[4];
    const float* wk   = (const float*)d_in[5];
    const float* wv   = (const float*)d_in[6];
    const float* wg   = (const float*)d_in[7];
    const float* bg   = (const float*)d_in[8];
    const float* wo   = (const float*)d_in[9];
    const float* bo   = (const float*)d_in[10];
    float* out = (float*)d_out;

    proj_kernel<<<dim3(M_TOT / BM, 4), 256>>>(q_x, kv_x, wq, wk, wv, wg, bg);
    attn_kernel<<<dim3(NRES, NH), 256>>>(mask, tri);
    outproj_kernel<<<dim3(M_TOT / BM), 256>>>(wo, bo, out);
}

// round 15
// speedup vs baseline: 1.3694x; 1.1199x over previous
#include <cuda_runtime.h>
#include <math.h>

// Problem constants: B=1, N=256, C_in=128, H=4, D=32
#define NRES 256
#define CIN  128
#define NH   4
#define DH   32
#define HD   128              // NH*DH
#define M_TOT (NRES * NRES)   // 65536 rows

typedef unsigned long long u64t;

// ---------------- packed f32x2 helpers (sm_100+ PTX; 2 FMAs per issue) ------
__device__ __forceinline__ u64t pack2(float lo, float hi) {
    u64t r; asm("mov.b64 %0, {%1, %2};" : "=l"(r) : "f"(lo), "f"(hi)); return r;
}
__device__ __forceinline__ u64t pack2r(float v) { return pack2(v, v); }
__device__ __forceinline__ void unpack2(u64t p, float& lo, float& hi) {
    asm("mov.b64 {%0, %1}, %2;" : "=f"(lo), "=f"(hi) : "l"(p));
}
__device__ __forceinline__ u64t ffma2_(u64t a, u64t b, u64t c) {
    u64t d; asm("fma.rn.f32x2 %0, %1, %2, %3;" : "=l"(d) : "l"(a), "l"(b), "l"(c)); return d;
}
__device__ __forceinline__ u64t fmul2_(u64t a, u64t b) {
    u64t d; asm("mul.rn.f32x2 %0, %1, %2;" : "=l"(d) : "l"(a), "l"(b)); return d;
}
__device__ __forceinline__ u64t fadd2_(u64t a, u64t b) {
    u64t d; asm("add.rn.f32x2 %0, %1, %2;" : "=l"(d) : "l"(a), "l"(b)); return d;
}

// ---------------- cp.async helpers ------------------------------------------
__device__ __forceinline__ void cp16(float* smem_dst, const float* gmem_src) {
    unsigned s = (unsigned)__cvta_generic_to_shared(smem_dst);
    asm volatile("cp.async.cg.shared.global [%0], [%1], 16;" :: "r"(s), "l"(gmem_src));
}
__device__ __forceinline__ void cp_commit() {
    asm volatile("cp.async.commit_group;");
}
__device__ __forceinline__ void cp_wait1() {
    asm volatile("cp.async.wait_group 1;");
}
__device__ __forceinline__ void cp_wait0() {
    asm volatile("cp.async.wait_group 0;");
}

// ---------------- scratch (static device globals; no allocation) ------------
__device__ float g_q[NRES * NH * NRES * DH];    // [n][h][q][d], pre-scaled
__device__ float g_k[NRES * NH * NRES * DH];    // [n][h][k][d]
__device__ float g_v[NRES * NH * NRES * DH];    // [n][h][k][d]
__device__ float g_gate[M_TOT * HD];            // [n*256+q][h*32+d], sigmoid applied
__device__ float g_o[M_TOT * HD];               // [n*256+q][h*32+d], attention out

// ---------------- tiled SGEMM config ----------------------------------------
#define BM 128
#define BN 128
#define BK 32
// 256 threads = 16x16, each computes 8x8 outputs (acc packed as 8x4 f32x2)

// Projections: modes 0=q (scaled), 1=k, 2=v, 3=gate (sigmoid(x+bg))
__global__ __launch_bounds__(256, 2)
void proj_kernel(const float* __restrict__ q_x, const float* __restrict__ kv_x,
                 const float* __restrict__ wq, const float* __restrict__ wk,
                 const float* __restrict__ wv, const float* __restrict__ wg,
                 const float* __restrict__ bg)
{
    __shared__ float As[BK][BM + 4];   // [k][m], stride 132 floats (16B-aligned rows)
    __shared__ float Bs[BK][BN + 4];

    const int mode = blockIdx.y;
    const float* A = (mode == 1 || mode == 2) ? kv_x : q_x;
    const float* W = (mode == 0) ? wq : (mode == 1) ? wk : (mode == 2) ? wv : wg;

    const int tid = threadIdx.x;
    const int tx = tid & 15;          // output col group
    const int ty = tid >> 4;          // output row group
    const int m0 = blockIdx.x * BM;
    const int ka = tid & 31;          // k within chunk (lane; coalesced global)
    const int mg = tid >> 5;          // 0..7 (warp id)

    u64t acc2[8][4];                  // [row][colpair], each = 2 fp32
#pragma unroll
    for (int i = 0; i < 8; i++)
#pragma unroll
        for (int jp = 0; jp < 4; jp++) acc2[i][jp] = 0ull;

    for (int k0 = 0; k0 < CIN; k0 += BK) {
        // staging: 4 coalesced row-loads per float4, conflict-free STS.128
#pragma unroll
        for (int i = 0; i < 4; i++) {
            int m = mg * 4 + i * 32;
            float a0 = A[(size_t)(m0 + m + 0) * CIN + k0 + ka];
            float a1 = A[(size_t)(m0 + m + 1) * CIN + k0 + ka];
            float a2 = A[(size_t)(m0 + m + 2) * CIN + k0 + ka];
            float a3 = A[(size_t)(m0 + m + 3) * CIN + k0 + ka];
            *(float4*)&As[ka][m] = make_float4(a0, a1, a2, a3);
            float b0 = W[(m + 0) * CIN + k0 + ka];
            float b1 = W[(m + 1) * CIN + k0 + ka];
            float b2 = W[(m + 2) * CIN + k0 + ka];
            float b3 = W[(m + 3) * CIN + k0 + ka];
            *(float4*)&Bs[ka][m] = make_float4(b0, b1, b2, b3);
        }
        __syncthreads();
#pragma unroll
        for (int kk = 0; kk < BK; kk++) {
            float a[8];
            *(float4*)&a[0] = *(float4*)&As[kk][ty * 8];
            *(float4*)&a[4] = *(float4*)&As[kk][ty * 8 + 4];
            ulonglong2 b01 = *(ulonglong2*)&Bs[kk][tx * 8];
            ulonglong2 b23 = *(ulonglong2*)&Bs[kk][tx * 8 + 4];
            u64t b2[4] = {b01.x, b01.y, b23.x, b23.y};
#pragma unroll
            for (int i = 0; i < 8; i++) {
                u64t a2 = pack2r(a[i]);
#pragma unroll
                for (int jp = 0; jp < 4; jp++)
                    acc2[i][jp] = ffma2_(a2, b2[jp], acc2[i][jp]);
            }
        }
        __syncthreads();
    }

    const int col0 = tx * 8;
    if (mode < 3) {
        const float scale = (mode == 0) ? 0.17677669529663687f : 1.0f;  // 1/sqrt(32)
        float* dst = (mode == 0) ? g_q : (mode == 1) ? g_k : g_v;
        const int h  = col0 >> 5;
        const int d0 = col0 & 31;     // 8 cols stay within one head
        const u64t scale2 = pack2r(scale);
#pragma unroll
        for (int i = 0; i < 8; i++) {
            int mrow = m0 + ty * 8 + i;
            int n = mrow >> 8, r = mrow & 255;
            float* p = dst + (((size_t)(n * NH + h) * NRES + r) * DH + d0);
            ulonglong2 s0, s1;
            s0.x = fmul2_(acc2[i][0], scale2);
            s0.y = fmul2_(acc2[i][1], scale2);
            s1.x = fmul2_(acc2[i][2], scale2);
            s1.y = fmul2_(acc2[i][3], scale2);
            *(ulonglong2*)p       = s0;
            *(ulonglong2*)(p + 4) = s1;
        }
    } else {
        float bgv[8];
#pragma unroll
        for (int j = 0; j < 8; j++) bgv[j] = bg[col0 + j];
#pragma unroll
        for (int i = 0; i < 8; i++) {
            int mrow = m0 + ty * 8 + i;
            float* p = g_gate + (size_t)mrow * HD + col0;
            float v[8];
            unpack2(acc2[i][0], v[0], v[1]);
            unpack2(acc2[i][1], v[2], v[3]);
            unpack2(acc2[i][2], v[4], v[5]);
            unpack2(acc2[i][3], v[6], v[7]);
#pragma unroll
            for (int j = 0; j < 8; j++) {
                float x = v[j] + bgv[j];
                v[j] = 1.0f / (1.0f + __expf(-x));
            }
            *(float4*)p       = make_float4(v[0], v[1], v[2], v[3]);
            *(float4*)(p + 4) = make_float4(v[4], v[5], v[6], v[7]);
        }
    }
}

// Output projection with gating fused into the A-tile load:
// out[m][c] = sum_e (g_o[m][e]*g_gate[m][e]) * wo[c][e] + bo[c]
__global__ __launch_bounds__(256, 2)
void outproj_kernel(const float* __restrict__ wo, const float* __restrict__ bo,
                    float* __restrict__ out)
{
    __shared__ float As[BK][BM + 4];
    __shared__ float Bs[BK][BN + 4];

    const int tid = threadIdx.x;
    const int tx = tid & 15, ty = tid >> 4;
    const int m0 = blockIdx.x * BM;
    const int ka = tid & 31, mg = tid >> 5;

    u64t acc2[8][4];
#pragma unroll
    for (int i = 0; i < 8; i++)
#pragma unroll
        for (int jp = 0; jp < 4; jp++) acc2[i][jp] = 0ull;

    for (int k0 = 0; k0 < HD; k0 += BK) {
#pragma unroll
        for (int i = 0; i < 4; i++) {
            int m = mg * 4 + i * 32;
            size_t i0 = (size_t)(m0 + m + 0) * HD + k0 + ka;
            size_t i1 = (size_t)(m0 + m + 1) * HD + k0 + ka;
            size_t i2 = (size_t)(m0 + m + 2) * HD + k0 + ka;
            size_t i3 = (size_t)(m0 + m + 3) * HD + k0 + ka;
            *(float4*)&As[ka][m] = make_float4(g_o[i0] * g_gate[i0],
                                               g_o[i1] * g_gate[i1],
                                               g_o[i2] * g_gate[i2],
                                               g_o[i3] * g_gate[i3]);
            float b0 = wo[(m + 0) * HD + k0 + ka];
            float b1 = wo[(m + 1) * HD + k0 + ka];
            float b2 = wo[(m + 2) * HD + k0 + ka];
            float b3 = wo[(m + 3) * HD + k0 + ka];
            *(float4*)&Bs[ka][m] = make_float4(b0, b1, b2, b3);
        }
        __syncthreads();
#pragma unroll
        for (int kk = 0; kk < BK; kk++) {
            float a[8];
            *(float4*)&a[0] = *(float4*)&As[kk][ty * 8];
            *(float4*)&a[4] = *(float4*)&As[kk][ty * 8 + 4];
            ulonglong2 b01 = *(ulonglong2*)&Bs[kk][tx * 8];
            ulonglong2 b23 = *(ulonglong2*)&Bs[kk][tx * 8 + 4];
            u64t b2[4] = {b01.x, b01.y, b23.x, b23.y};
#pragma unroll
            for (int i = 0; i < 8; i++) {
                u64t a2 = pack2r(a[i]);
#pragma unroll
                for (int jp = 0; jp < 4; jp++)
                    acc2[i][jp] = ffma2_(a2, b2[jp], acc2[i][jp]);
            }
        }
        __syncthreads();
    }

    const int col0 = tx * 8;
    ulonglong2 bo01 = *(const ulonglong2*)(bo + col0);
    ulonglong2 bo23 = *(const ulonglong2*)(bo + col0 + 4);
    u64t bo2[4] = {bo01.x, bo01.y, bo23.x, bo23.y};
#pragma unroll
    for (int i = 0; i < 8; i++) {
        int mrow = m0 + ty * 8 + i;
        float* p = out + (size_t)mrow * HD + col0;
        ulonglong2 s0, s1;
        s0.x = fadd2_(acc2[i][0], bo2[0]);
        s0.y = fadd2_(acc2[i][1], bo2[1]);
        s1.x = fadd2_(acc2[i][2], bo2[2]);
        s1.y = fadd2_(acc2[i][3], bo2[3]);
        *(ulonglong2*)p       = s0;
        *(ulonglong2*)(p + 4) = s1;
    }
}

// ---------------- attention smem layout (dynamic, ping-pong stages) ---------
// stage (floats): Ks[32][36] | Vs[32][36] | Ts[256][36]   (rows 16B-aligned)
#define KS_OFF   0
#define VS_OFF   (32 * 36)
#define TS_OFF   (2 * 32 * 36)
#define STAGE_F  (TS_OFF + 256 * 36)          // 11520 floats = 46080 B
#define MB_OFF   (2 * STAGE_F)                // after both stages
#define ATTN_SMEM_BYTES ((MB_OFF + NRES) * 4) // 93,184 B

// Fused attention: one block per (n,h), one thread per q row, online softmax.
// K/V/tri staged via cp.async double-buffering (no register prefetch state).
// Ts/MB read as full-bandwidth float4 pairs; all math in packed f32x2; rescale
// amortized per 8-k sub-chunk and skipped (bit-exact) when max doesn't rise.
// min-blocks=2 guarantees 2 CTAs/SM (regs <= 128); smem already permits it.
__global__ __launch_bounds__(256, 2)
void attn_kernel(const float* __restrict__ mask_bias,
                 const float* __restrict__ tri)
{
    extern __shared__ float sm[];
    const int n = blockIdx.x;
    const int h = blockIdx.y;
    const int q = threadIdx.x;   // 0..255

    const size_t base = (size_t)(n * NH + h) * NRES * DH;
    const float* Qg = g_q + base;
    const float* Kg = g_k + base;
    const float* Vg = g_v + base;
    const float* trib = tri + (size_t)(h * NRES) * NRES;

    const int lr  = threadIdx.x >> 3;        // 0..31
    const int lc4 = (threadIdx.x & 7) * 4;   // 0,4,...,28

    // mask bias row for this n (read as broadcast float4 in the score loop)
    sm[MB_OFF + q] = mask_bias[n * NRES + q];

    u64t qv2[16];                     // q row packed along d
#pragma unroll
    for (int i = 0; i < 8; i++) {
        ulonglong2 t = ((const ulonglong2*)(Qg + q * DH))[i];
        qv2[i * 2] = t.x; qv2[i * 2 + 1] = t.y;
    }

    float mx = -1e30f, l = 0.f;
    u64t o2[16];
#pragma unroll
    for (int dp = 0; dp < 16; dp++) o2[dp] = 0ull;

    // ---- prologue: stage 0 via cp.async ----
    {
        float* S = sm;
        cp16(S + KS_OFF + lr * 36 + lc4, Kg + lr * DH + lc4);
        cp16(S + VS_OFF + lr * 36 + lc4, Vg + lr * DH + lc4);
#pragma unroll
        for (int i = 0; i < 8; i++)
            cp16(S + TS_OFF + (lr + i * 32) * 36 + lc4,
                 trib + (size_t)(lr + i * 32) * NRES + lc4);
        cp_commit();
    }

    for (int k0 = 0; k0 < NRES; k0 += 32) {
        const int buf = (k0 >> 5) & 1;
        // issue next stage, then wait for current
        int kn = k0 + 32;
        if (kn < NRES) {
            float* S = sm + (buf ^ 1) * STAGE_F;
            cp16(S + KS_OFF + lr * 36 + lc4, Kg + (kn + lr) * DH + lc4);
            cp16(S + VS_OFF + lr * 36 + lc4, Vg + (kn + lr) * DH + lc4);
#pragma unroll
            for (int i = 0; i < 8; i++)
                cp16(S + TS_OFF + (lr + i * 32) * 36 + lc4,
                     trib + (size_t)(lr + i * 32) * NRES + kn + lc4);
            cp_commit();
            cp_wait1();
        } else {
            cp_wait0();
        }
        __syncthreads();   // current stage visible to all (also orders MB on iter 0)

        const float* Ks = sm + buf * STAGE_F + KS_OFF;
        const float* Vs = sm + buf * STAGE_F + VS_OFF;
        const float* Ts = sm + buf * STAGE_F + TS_OFF + q * 36;
        const float* MBc = sm + MB_OFF + k0;

#pragma unroll
        for (int kc = 0; kc < 32; kc += 8) {
            // --- bias: 2 full-bandwidth float4 LDS + broadcast float4 MB ---
            float4 t0 = *(const float4*)(Ts + kc);
            float4 t1 = *(const float4*)(Ts + kc + 4);
            float4 mb0 = *(const float4*)(MBc + kc);
            float4 mb1 = *(const float4*)(MBc + kc + 4);
            float bias[8] = {t0.x + mb0.x, t0.y + mb0.y, t0.z + mb0.z, t0.w + mb0.w,
                             t1.x + mb1.x, t1.y + mb1.y, t1.z + mb1.z, t1.w + mb1.w};
            // --- phase 1: 8 scores, packed dual accumulators ---
            float s[8];
#pragma unroll
            for (int j = 0; j < 8; j++) {
                int kk = kc + j;
                const float* Kr = Ks + kk * 36;
                u64t accA = 0ull, accB = 0ull;
#pragma unroll
                for (int d = 0; d < 32; d += 4) {
                    ulonglong2 k2 = *(const ulonglong2*)(Kr + d);   // broadcast
                    accA = ffma2_(qv2[d >> 1], k2.x, accA);
                    accB = ffma2_(qv2[(d >> 1) + 1], k2.y, accB);
                }
                float aLo, aHi, bLo, bHi;
                unpack2(accA, aLo, aHi);
                unpack2(accB, bLo, bHi);
                s[j] = bias[j] + ((aLo + aHi) + (bLo + bHi));
            }
            // --- phase 2: sub-chunk max; rescale only if running max rises ---
            float cmax = s[0];
#pragma unroll
            for (int j = 1; j < 8; j++) cmax = fmaxf(cmax, s[j]);
            if (cmax > mx) {
                float corr = __expf(mx - cmax);   // exact no-op path skipped
                mx = cmax;
                l *= corr;
                u64t corr2 = pack2r(corr);
#pragma unroll
                for (int dp = 0; dp < 16; dp++) o2[dp] = fmul2_(o2[dp], corr2);
            }
            // --- phase 3: packed-FMA accumulate ---
#pragma unroll
            for (int j = 0; j < 8; j++) {
                int kk = kc + j;
                const float* Vr = Vs + kk * 36;
                float p = __expf(s[j] - mx);
                l += p;
                u64t p2 = pack2r(p);
#pragma unroll
                for (int d = 0; d < 32; d += 4) {
                    ulonglong2 v2 = *(const ulonglong2*)(Vr + d);
                    o2[d >> 1]       = ffma2_(p2, v2.x, o2[d >> 1]);
                    o2[(d >> 1) + 1] = ffma2_(p2, v2.y, o2[(d >> 1) + 1]);
                }
            }
        }
        __syncthreads();   // all done reading buf before it is refilled
    }

    const float inv = 1.0f / l;
    const u64t inv2 = pack2r(inv);
    float* Og = g_o + ((size_t)(n * NRES + q)) * HD + h * DH;
#pragma unroll
    for (int dp = 0; dp < 16; dp += 2) {
        ulonglong2 st;
        st.x = fmul2_(o2[dp], inv2);
        st.y = fmul2_(o2[dp + 1], inv2);
        *(ulonglong2*)(Og + dp * 2) = st;
    }
}

// ---------------------------------------------------------------------------
extern "C" void kernel_launch(void* const* d_in, const int* in_sizes, int n_in,
                              void* d_out, int out_size)
{
    (void)in_sizes; (void)n_in; (void)out_size;
    const float* q_x  = (const float*)d_in[0];
    const float* kv_x = (const float*)d_in[1];
    const float* mask = (const float*)d_in[2];
    const float* tri  = (const float*)d_in[3];
    const float* wq   = (const float*)d_in[4];
    const float* wk   = (const float*)d_in[5];
    const float* wv   = (const float*)d_in[6];
    const float* wg   = (const float*)d_in[7];
    const float* bg   = (const float*)d_in[8];
    const float* wo   = (const float*)d_in[9];
    const float* bo   = (const float*)d_in[10];
    float* out = (float*)d_out;

    // unconditional (no static state): cheap host-side attribute set
    cudaFuncSetAttribute(attn_kernel,
                         cudaFuncAttributeMaxDynamicSharedMemorySize,
                         ATTN_SMEM_BYTES);

    proj_kernel<<<dim3(M_TOT / BM, 4), 256>>>(q_x, kv_x, wq, wk, wv, wg, bg);
    attn_kernel<<<dim3(NRES, NH), 256, ATTN_SMEM_BYTES>>>(mask, tri);
    outproj_kernel<<<dim3(M_TOT / BM), 256>>>(wo, bo, out);
}